// round 8
// baseline (speedup 1.0000x reference)
#include <cuda_runtime.h>
#include <cstdint>

#define B    256
#define T    1024
#define H    256
#define INP  32
#define OUTD 32
#define G3   768
#define NC   128
#define THR  512

typedef unsigned long long u64;

// Static device scratch (allocation-free rule)
__device__ float g_obsT[(size_t)T * INP * B];       // [t][i][b]
__device__ float g_Hst[(size_t)(T + 1) * H * B];    // [t][h][b], t=0 zero (BSS)
__device__ float g_M[4 * H * H];
__device__ float g_C[G3 * B];
__device__ float g_C0[G3 * B];
// packed operand tables
__device__ u64 g_Mp[32 * 256 * 4 * 4];              // [g4][k][s][gate]
__device__ u64 g_Wop[32 * 32 * 4 * 4];              // [g4][i][s][gate]
__device__ u64 g_Cp[3 * 128 * B];                   // [gate][P][b]
__device__ u64 g_C0p[3 * 128 * B];
__device__ u64 g_bp[128];
__device__ unsigned g_flags[NC];

// SMEM layout (bytes)
#define SM_M    0
#define SM_H2   32768
#define SM_C    163840
#define SM_C0   169984
#define SM_W    176128
#define SM_RED  180224
#define SM_TOT  188416

__device__ __forceinline__ u64 pack2(float x, float y) {
    u64 r; asm("mov.b64 %0,{%1,%2};" : "=l"(r) : "f"(x), "f"(y)); return r;
}
__device__ __forceinline__ void unpack2(u64 v, float& x, float& y) {
    asm("mov.b64 {%0,%1},%2;" : "=f"(x), "=f"(y) : "l"(v));
}
__device__ __forceinline__ u64 fma2(u64 a, u64 b, u64 c) {
    u64 d; asm("fma.rn.f32x2 %0,%1,%2,%3;" : "=l"(d) : "l"(a), "l"(b), "l"(c)); return d;
}
__device__ __forceinline__ u64 add2(u64 a, u64 b) {
    u64 d; asm("add.rn.f32x2 %0,%1,%2;" : "=l"(d) : "l"(a), "l"(b)); return d;
}
__device__ __forceinline__ float sigf(float x) {
    return __fdividef(1.0f, 1.0f + __expf(-x));
}
__device__ __forceinline__ float tanhx(float x) {
    return __fdividef(2.0f, 1.0f + __expf(-2.0f * x)) - 1.0f;
}
__device__ __forceinline__ void st_release(unsigned* p, unsigned v) {
    asm volatile("st.global.release.gpu.b32 [%0], %1;" :: "l"(p), "r"(v) : "memory");
}
__device__ __forceinline__ unsigned ld_acquire(const unsigned* p) {
    unsigned v;
    asm volatile("ld.global.acquire.gpu.b32 %0, [%1];" : "=r"(v) : "l"(p) : "memory");
    return v;
}

// ---------------------------------------------------------------------------
__global__ void k_transpose(const float* __restrict__ obs) {
    int t = blockIdx.x, b = threadIdx.x;
    const float4* src = (const float4*)(obs + (size_t)b * T * INP + (size_t)t * INP);
    float4 v[8];
#pragma unroll
    for (int q = 0; q < 8; q++) v[q] = src[q];
    float* dst = g_obsT + (size_t)t * (INP * B) + b;
#pragma unroll
    for (int q = 0; q < 8; q++) {
        dst[(4 * q + 0) * B] = v[q].x;
        dst[(4 * q + 1) * B] = v[q].y;
        dst[(4 * q + 2) * B] = v[q].z;
        dst[(4 * q + 3) * B] = v[q].w;
    }
}

// ---------------------------------------------------------------------------
// Merged recurrent matrix M (1024 x 256)
__global__ void k_prep_M(const float* __restrict__ W_ih,
                         const float* __restrict__ W_hh,
                         const float* __restrict__ W_out) {
    int j = blockIdx.x, k = threadIdx.x;
    float v;
    if (j < 768) {
        float comb = 0.f;
#pragma unroll
        for (int o = 0; o < 32; o++)
            comb = fmaf(W_ih[j * 96 + 32 + o], W_out[o * H + k], comb);
        v = (j < 512) ? (W_hh[j * H + k] + comb) : comb;
    } else {
        v = W_hh[(j - 256) * H + k];
    }
    g_M[j * H + k] = v;
}

// ---------------------------------------------------------------------------
__global__ void k_prep_C(const float* __restrict__ z_dyn,
                         const float* __restrict__ init_y,
                         const float* __restrict__ W_ih,
                         const float* __restrict__ b_ih,
                         const float* __restrict__ b_hh,
                         const float* __restrict__ b_out) {
    int j = blockIdx.x, b = threadIdx.x;
    float zp = 0.f, yb = 0.f, iy = 0.f;
#pragma unroll
    for (int i = 0; i < 32; i++)
        zp = fmaf(z_dyn[b * 32 + i], W_ih[j * 96 + 64 + i], zp);
#pragma unroll
    for (int o = 0; o < 32; o++) {
        float wy = W_ih[j * 96 + 32 + o];
        yb = fmaf(b_out[o], wy, yb);
        iy = fmaf(init_y[b * 32 + o], wy, iy);
    }
    float base = b_ih[j] + (j < 512 ? b_hh[j] : 0.f);
    g_C[j * B + b]  = zp + base + yb;
    g_C0[j * B + b] = zp + base + iy;
}

// ---------------------------------------------------------------------------
// Pack kernels
__global__ void k_pack_M() {
    int idx = blockIdx.x * 256 + threadIdx.x;          // 131072
    int g4 = idx >> 12, rem = idx & 4095;
    int k = rem >> 4, s = (rem >> 2) & 3, g = rem & 3;
    int row = g * H + g4 * 8 + 2 * s;
    g_Mp[idx] = pack2(g_M[row * H + k], g_M[(row + 1) * H + k]);
}
__global__ void k_pack_W(const float* __restrict__ W_ih) {
    int idx = blockIdx.x * 256 + threadIdx.x;          // 16384
    int g4 = idx >> 9, rem = idx & 511;
    int i = rem >> 4, s = (rem >> 2) & 3, g = rem & 3;
    u64 v = 0;
    if (g < 3) {
        int row = g * H + g4 * 8 + 2 * s;
        v = pack2(W_ih[row * 96 + i], W_ih[(row + 1) * 96 + i]);
    }
    g_Wop[idx] = v;
}
__global__ void k_pack_C() {
    int idx = blockIdx.x * 256 + threadIdx.x;          // 98304
    int g = idx >> 15, rem = idx & 32767;
    int P = rem >> 8, b = rem & 255;
    int row = g * H + 2 * P;
    g_Cp[idx]  = pack2(g_C [row * B + b], g_C [(row + 1) * B + b]);
    g_C0p[idx] = pack2(g_C0[row * B + b], g_C0[(row + 1) * B + b]);
}
__global__ void k_pack_b(const float* __restrict__ b_hh) {
    int P = threadIdx.x;
    g_bp[P] = pack2(b_hh[2 * H + 2 * P], b_hh[2 * H + 2 * P + 1]);
}

// ---------------------------------------------------------------------------
// Persistent GRU loop, K-split, SMEM-staged h.
// CTA c: h-cols [8*(c>>2), +8), batches [(c&3)*64, +64).
// Thread: kh = tid>>8, r = tid&255, s = r>>6, bl = r&63.
__global__ void __launch_bounds__(THR, 1)
k_rnn() {
    extern __shared__ __align__(16) char smem[];
    u64* m_s    = (u64*)(smem + SM_M);    // [k][s][g] : k*16 + s*4 + g
    u64* h2_s   = (u64*)(smem + SM_H2);   // [k][bl]   : k*64 + bl (dup pairs)
    u64* c_s    = (u64*)(smem + SM_C);    // [g][r]    : g*256 + r
    u64* c0_s   = (u64*)(smem + SM_C0);   // [g][r]
    u64* wobs_s = (u64*)(smem + SM_W);    // [i][s][g] : i*16 + s*4 + g
    u64* red_s  = (u64*)(smem + SM_RED);  // [r][4]

    const int tid = threadIdx.x;
    const int cta = blockIdx.x;
    const int g4  = cta >> 2;
    const int bg  = cta & 3;
    const int hcb = g4 * 8;
    const int kh  = tid >> 8;
    const int r   = tid & 255;
    const int s   = r >> 6;
    const int bl  = r & 63;
    const int b   = bg * 64 + bl;
    const int P   = g4 * 4 + s;
    const int k0  = kh * 128;

    // fill M / weights / constants (coalesced from packed tables)
    {
        const float4* msrc = (const float4*)g_Mp + (size_t)g4 * 2048;
        float4* mdst = (float4*)m_s;
#pragma unroll
        for (int e = 0; e < 4; e++) mdst[e * 512 + tid] = msrc[e * 512 + tid];
        const float4* wsrc = (const float4*)g_Wop + (size_t)g4 * 256;
        if (tid < 256) {
            ((float4*)wobs_s)[tid] = wsrc[tid];
#pragma unroll
            for (int g = 0; g < 3; g++) {
                int pp = g4 * 4 + (tid >> 6);
                int bb = bg * 64 + (tid & 63);
                c_s [g * 256 + tid] = g_Cp [(g * 128 + pp) * B + bb];
                c0_s[g * 256 + tid] = g_C0p[(g * 128 + pp) * B + bb];
            }
        }
    }
    const u64 bhh2 = g_bp[P];
    __syncthreads();

    const unsigned base = ld_acquire(&g_flags[cta]);

    for (int t = 0; t < T; t++) {
        // ---- cooperative h staging: 8 independent LDG.128 per thread ----
        const float* hrow = g_Hst + (size_t)t * (H * B) + bg * 64;
        float4 stg[8];
#pragma unroll
        for (int j = 0; j < 8; j++) {
            int f = tid * 8 + j;            // float4 index in [0,4096)
            int k = f >> 4, c = f & 15;
            stg[j] = *(const float4*)(hrow + k * B + c * 4);
        }

        // constants + obs loads issued while h lands (kh==0 threads)
        u64 aR, aZ, aN, aH;
        float ov[32];
        if (kh == 0) {
            const u64* cs = (t == 0) ? c0_s : c_s;
            aR = cs[0 * 256 + r];
            aZ = cs[1 * 256 + r];
            aN = cs[2 * 256 + r];
            aH = bhh2;
            const float* op = g_obsT + (size_t)t * (INP * B) + b;
#pragma unroll
            for (int i = 0; i < 32; i++) ov[i] = op[i * B];
        } else {
            aR = 0; aZ = 0; aN = 0; aH = 0;
        }

        // store h as duplicated pairs
#pragma unroll
        for (int j = 0; j < 8; j++) {
            int f = tid * 8 + j;
            int k = f >> 4, c = f & 15;
            u64* d = &h2_s[k * 64 + c * 4];
            ulonglong2 p0, p1;
            p0.x = pack2(stg[j].x, stg[j].x);
            p0.y = pack2(stg[j].y, stg[j].y);
            p1.x = pack2(stg[j].z, stg[j].z);
            p1.y = pack2(stg[j].w, stg[j].w);
            *(ulonglong2*)(d)     = p0;
            *(ulonglong2*)(d + 2) = p1;
        }

        // obs contribution (kh0) overlaps other warps' STS
        if (kh == 0) {
#pragma unroll
            for (int i = 0; i < 32; i++) {
                u64 o2 = pack2(ov[i], ov[i]);
                const u64* w = &wobs_s[i * 16 + s * 4];
                ulonglong2 w01 = *(const ulonglong2*)w;
                u64 w2v = w[2];
                aR = fma2(o2, w01.x, aR);
                aZ = fma2(o2, w01.y, aZ);
                aN = fma2(o2, w2v, aN);
            }
        }
        __syncthreads();   // h2_s ready

        // ---- recurrent GEMM from SMEM: 128 k per thread ----
        const u64* hp2 = h2_s + (size_t)k0 * 64 + bl;
        const u64* mp  = m_s + (size_t)k0 * 16 + s * 4;
#pragma unroll 4
        for (int j = 0; j < 16; j++) {
#pragma unroll
            for (int q = 0; q < 8; q++) {
                int k = j * 8 + q;
                u64 h2 = hp2[k * 64];
                ulonglong2 m01 = *(const ulonglong2*)(mp + k * 16);
                ulonglong2 m23 = *(const ulonglong2*)(mp + k * 16 + 2);
                aR = fma2(h2, m01.x, aR);
                aZ = fma2(h2, m01.y, aZ);
                aN = fma2(h2, m23.x, aN);
                aH = fma2(h2, m23.y, aH);
            }
        }

        // cross-half reduction
        if (kh == 1) {
            ulonglong2* rd = (ulonglong2*)&red_s[r * 4];
            rd[0] = make_ulonglong2(aR, aZ);
            rd[1] = make_ulonglong2(aN, aH);
        }
        __syncthreads();

        if (kh == 0) {
            ulonglong2 p01 = *(const ulonglong2*)&red_s[r * 4];
            ulonglong2 p23 = *(const ulonglong2*)&red_s[r * 4 + 2];
            aR = add2(aR, p01.x);
            aZ = add2(aZ, p01.y);
            aN = add2(aN, p23.x);
            aH = add2(aH, p23.y);

            // previous h for own columns (lo half of duplicated pair)
            float hp0, hp1, dum;
            unpack2(h2_s[(hcb + 2 * s) * 64 + bl], hp0, dum);
            unpack2(h2_s[(hcb + 2 * s + 1) * 64 + bl], hp1, dum);

            float xr0, xr1, xz0, xz1, xn0, xn1, hn0, hn1;
            unpack2(aR, xr0, xr1); unpack2(aZ, xz0, xz1);
            unpack2(aN, xn0, xn1); unpack2(aH, hn0, hn1);
            float r0 = sigf(xr0), r1 = sigf(xr1);
            float z0 = sigf(xz0), z1 = sigf(xz1);
            float n0 = tanhx(fmaf(r0, hn0, xn0));
            float n1 = tanhx(fmaf(r1, hn1, xn1));
            float h0 = fmaf(z0, hp0 - n0, n0);
            float h1 = fmaf(z1, hp1 - n1, n1);

            float* hd = g_Hst + (size_t)(t + 1) * (H * B);
            hd[(hcb + 2 * s) * B + b]     = h0;
            hd[(hcb + 2 * s + 1) * B + b] = h1;
        }

        // ---- release/acquire barrier over the 32 CTAs of this batch group ----
        __syncthreads();
        const unsigned tgt = base + (unsigned)(t + 1);
        if (tid == 0) st_release(&g_flags[cta], tgt);
        if (tid < 32) {
            const unsigned* f = &g_flags[(tid << 2) | bg];
            while ((int)(ld_acquire(f) - tgt) < 0) { }
        }
        __syncthreads();
    }
}

// ---------------------------------------------------------------------------
__global__ void __launch_bounds__(256)
k_out(const float* __restrict__ W_out, const float* __restrict__ b_out,
      float* __restrict__ out) {
    __shared__ u64 w2[16][H];
    int t = blockIdx.x, b = threadIdx.x;
#pragma unroll
    for (int p = 0; p < 16; p++)
        w2[p][b] = pack2(W_out[(2 * p) * H + b], W_out[(2 * p + 1) * H + b]);
    __syncthreads();

    u64 acc[16];
#pragma unroll
    for (int p = 0; p < 16; p++) acc[p] = pack2(b_out[2 * p], b_out[2 * p + 1]);

    const float* hs = g_Hst + (size_t)(t + 1) * (H * B) + b;
#pragma unroll 4
    for (int h = 0; h < H; h++) {
        float hv = hs[h * B];
        u64 hv2 = pack2(hv, hv);
#pragma unroll
        for (int p = 0; p < 16; p++) acc[p] = fma2(hv2, w2[p][h], acc[p]);
    }
    float* o = out + (size_t)b * (T * OUTD) + (size_t)t * OUTD;
#pragma unroll
    for (int p = 0; p < 16; p++) {
        float x, y; unpack2(acc[p], x, y);
        o[2 * p] = x; o[2 * p + 1] = y;
    }
}

// ---------------------------------------------------------------------------
extern "C" void kernel_launch(void* const* d_in, const int* in_sizes, int n_in,
                              void* d_out, int out_size) {
    const float* init_y = (const float*)d_in[0];
    const float* obs    = (const float*)d_in[1];
    const float* z_dyn  = (const float*)d_in[2];
    const float* W_ih   = (const float*)d_in[3];
    const float* W_hh   = (const float*)d_in[4];
    const float* b_ih   = (const float*)d_in[5];
    const float* b_hh   = (const float*)d_in[6];
    const float* W_out  = (const float*)d_in[7];
    const float* b_out  = (const float*)d_in[8];
    float* out = (float*)d_out;

    cudaFuncSetAttribute(k_rnn, cudaFuncAttributeMaxDynamicSharedMemorySize, SM_TOT);

    k_transpose<<<T, B>>>(obs);
    k_prep_M<<<1024, H>>>(W_ih, W_hh, W_out);
    k_prep_C<<<G3, B>>>(z_dyn, init_y, W_ih, b_ih, b_hh, b_out);
    k_pack_M<<<512, 256>>>();
    k_pack_W<<<64, 256>>>(W_ih);
    k_pack_C<<<384, 256>>>();
    k_pack_b<<<1, 128>>>(b_hh);
    k_rnn<<<NC, THR, SM_TOT>>>();
    k_out<<<T, B>>>(W_out, b_out, out);
}